// round 1
// baseline (speedup 1.0000x reference)
#include <cuda_runtime.h>

#define NTOK 20
#define NT   24          // padded token stride (floats), 16B-aligned rows
#define TPB  128

// ---------- packed f32x2 helpers ----------
__device__ __forceinline__ unsigned long long pk2(float lo, float hi) {
    unsigned long long r;
    asm("mov.b64 %0, {%1,%2};" : "=l"(r)
        : "r"(__float_as_uint(lo)), "r"(__float_as_uint(hi)));
    return r;
}
__device__ __forceinline__ void upk2(unsigned long long v, float& lo, float& hi) {
    unsigned int a, b;
    asm("mov.b64 {%0,%1}, %2;" : "=r"(a), "=r"(b) : "l"(v));
    lo = __uint_as_float(a); hi = __uint_as_float(b);
}
__device__ __forceinline__ void fma2(unsigned long long& d,
                                     unsigned long long a, unsigned long long b) {
    asm("fma.rn.f32x2 %0, %1, %2, %0;" : "+l"(d) : "l"(a), "l"(b));
}

// ---------- dense layer: in_sh is feature-major [FI][NT], out feature-major [FO][NT] ----------
template<int FI, int FO, bool RELU>
__device__ __forceinline__ void dense(const float* __restrict__ W,
                                      const float* __restrict__ Bv,
                                      const float* in_sh, float* out_sh) {
    const int tid = threadIdx.x;
    for (int j = tid; j < FO; j += TPB) {
        const float bj = Bv[j];
        unsigned long long acc[10];
        #pragma unroll
        for (int k = 0; k < 10; k++) acc[k] = pk2(bj, bj);
        #pragma unroll 4
        for (int i = 0; i < FI; i++) {
            const float w = W[i * FO + j];
            const unsigned long long wd = pk2(w, w);
            const ulonglong2* p = reinterpret_cast<const ulonglong2*>(in_sh + i * NT);
            #pragma unroll
            for (int q = 0; q < 5; q++) {
                ulonglong2 v = p[q];
                fma2(acc[2*q],   v.x, wd);
                fma2(acc[2*q+1], v.y, wd);
            }
        }
        #pragma unroll
        for (int k = 0; k < 10; k++) {
            float a, b; upk2(acc[k], a, b);
            if (RELU) { a = fmaxf(a, 0.f); b = fmaxf(b, 0.f); }
            out_sh[j * NT + 2*k]     = a;
            out_sh[j * NT + 2*k + 1] = b;
        }
    }
}

// ---------- dense with concat input: [per-token features F1] ++ [token-invariant vector FG] ----------
template<int F1, int FG, int FO, bool RELU>
__device__ __forceinline__ void dense_cat(const float* __restrict__ W,
                                          const float* __restrict__ Bv,
                                          const float* in_sh, const float* gv,
                                          float* out_sh) {
    const int tid = threadIdx.x;
    for (int j = tid; j < FO; j += TPB) {
        // token-invariant half folded into the bias (1 FMA per input instead of 20)
        float s = Bv[j];
        #pragma unroll 4
        for (int i = 0; i < FG; i++) s = fmaf(gv[i], W[(F1 + i) * FO + j], s);
        unsigned long long acc[10];
        #pragma unroll
        for (int k = 0; k < 10; k++) acc[k] = pk2(s, s);
        #pragma unroll 4
        for (int i = 0; i < F1; i++) {
            const float w = W[i * FO + j];
            const unsigned long long wd = pk2(w, w);
            const ulonglong2* p = reinterpret_cast<const ulonglong2*>(in_sh + i * NT);
            #pragma unroll
            for (int q = 0; q < 5; q++) {
                ulonglong2 v = p[q];
                fma2(acc[2*q],   v.x, wd);
                fma2(acc[2*q+1], v.y, wd);
            }
        }
        #pragma unroll
        for (int k = 0; k < 10; k++) {
            float a, b; upk2(acc[k], a, b);
            if (RELU) { a = fmaxf(a, 0.f); b = fmaxf(b, 0.f); }
            out_sh[j * NT + 2*k]     = a;
            out_sh[j * NT + 2*k + 1] = b;
        }
    }
}

__global__ void __launch_bounds__(TPB)
sp_kernel(const float* __restrict__ state,
          const float* __restrict__ m1w0, const float* __restrict__ m1b0,
          const float* __restrict__ m1w1, const float* __restrict__ m1b1,
          const float* __restrict__ m2w0, const float* __restrict__ m2b0,
          const float* __restrict__ m2w1, const float* __restrict__ m2b1,
          const float* __restrict__ atw0, const float* __restrict__ atb0,
          const float* __restrict__ atw1, const float* __restrict__ atb1,
          const float* __restrict__ atw2, const float* __restrict__ atb2,
          const float* __restrict__ hpw0, const float* __restrict__ hpb0,
          const float* __restrict__ hpw1, const float* __restrict__ hpb1,
          const float* __restrict__ hpw2, const float* __restrict__ hpb2,
          float* __restrict__ out)
{
    __shared__ __align__(16) float x_sh[13 * NT];
    __shared__ __align__(16) float h1_sh[100 * NT];
    __shared__ __align__(16) float h2_sh[50 * NT];
    __shared__ __align__(16) float tA[150 * NT];
    __shared__ __align__(16) float tB[100 * NT];
    __shared__ float g_sh[100];
    __shared__ float ws_sh[64];
    __shared__ float mask_sh[NTOK];
    __shared__ float se_sh[NTOK];
    __shared__ float w_sh[NTOK];

    const int b   = blockIdx.x;
    const int tid = threadIdx.x;

    // ---- load state tile: 20 tokens x (13 feats + mask), feature-major ----
    const float* st = state + (size_t)b * (NTOK * 14);
    for (int t = tid; t < NTOK * 14; t += TPB) {
        float v = st[t];
        int n = t / 14, d = t % 14;
        if (d == 13) mask_sh[n] = v;
        else         x_sh[d * NT + n] = v;
    }
    __syncthreads();

    // ---- m1: 13 -> 150 (relu) -> 100 (relu) ----
    dense<13, 150, true>(m1w0, m1b0, x_sh, tA);
    __syncthreads();
    dense<150, 100, true>(m1w1, m1b1, tA, h1_sh);
    __syncthreads();

    // ---- masked mean of h1 over tokens -> g_sh[100] ----
    if (tid < 100) {
        float msum = 0.f;
        #pragma unroll
        for (int n = 0; n < NTOK; n++) msum += mask_sh[n];
        const float inv = (msum > 0.f) ? 1.f / msum : 0.f;
        float gj = 0.f;
        #pragma unroll
        for (int n = 0; n < NTOK; n++) gj += mask_sh[n] * h1_sh[tid * NT + n];
        g_sh[tid] = gj * inv;
    }
    __syncthreads();

    // ---- m2: h1 -> 100 (relu) -> 50 (no relu) ----
    dense<100, 100, true>(m2w0, m2b0, h1_sh, tB);
    __syncthreads();
    dense<100, 50, false>(m2w1, m2b1, tB, h2_sh);
    __syncthreads();

    // ---- attention MLP: concat(h1, g) -> 100 (relu) -> 100 (relu) -> 1 ----
    dense_cat<100, 100, 100, true>(atw0, atb0, h1_sh, g_sh, tA);
    __syncthreads();
    dense<100, 100, true>(atw1, atb1, tA, tB);
    __syncthreads();

    if (tid < NTOK) {
        float s = atb2[0];
        #pragma unroll 4
        for (int i = 0; i < 100; i++) s = fmaf(tB[i * NT + tid], atw2[i], s);
        s *= mask_sh[tid];
        se_sh[tid] = (s != 0.f) ? expf(s) : 0.f;
    }
    __syncthreads();
    if (tid < NTOK) {
        float ssum = 0.f;
        #pragma unroll
        for (int n = 0; n < NTOK; n++) ssum += se_sh[n];
        w_sh[tid] = (ssum > 0.f) ? se_sh[tid] / ssum : 0.f;
    }
    __syncthreads();

    // ---- weighted sum of h2 -> ws_sh[50] ----
    if (tid < 50) {
        float s = 0.f;
        #pragma unroll
        for (int n = 0; n < NTOK; n++) s += w_sh[n] * h2_sh[tid * NT + n];
        ws_sh[tid] = s;
    }
    __syncthreads();

    // ---- head: concat(h2, wsum) -> 100 (relu) -> 100 (relu) -> 7 ----
    dense_cat<50, 50, 100, true>(hpw0, hpb0, h2_sh, ws_sh, tA);
    __syncthreads();
    dense<100, 100, true>(hpw1, hpb1, tA, tB);
    __syncthreads();

    // ---- final 100 -> 7, thread = (token-pair, neuron) ----
    if (tid < 70) {
        const int kp = tid / 7, j = tid % 7;
        unsigned long long acc = pk2(hpb2[j], hpb2[j]);
        #pragma unroll 4
        for (int i = 0; i < 100; i++) {
            const float w = hpw2[i * 7 + j];
            unsigned long long v =
                *reinterpret_cast<const unsigned long long*>(tB + i * NT + 2 * kp);
            fma2(acc, v, pk2(w, w));
        }
        float a, c; upk2(acc, a, c);
        float* ob = out + (size_t)b * (NTOK * 7);
        ob[(2 * kp)     * 7 + j] = a;
        ob[(2 * kp + 1) * 7 + j] = c;
    }
}

extern "C" void kernel_launch(void* const* d_in, const int* in_sizes, int n_in,
                              void* d_out, int out_size) {
    // state is the only huge tensor (B*20*14 elems). Dict order puts it last,
    // signature order puts it first — detect by size.
    int si, wb;
    if (in_sizes[0] > 1000000) { si = 0;        wb = 1; }
    else                       { si = n_in - 1; wb = 0; }
    const float* state = (const float*)d_in[si];
    const int B = in_sizes[si] / (NTOK * 14);

    sp_kernel<<<B, TPB>>>(
        state,
        (const float*)d_in[wb + 0],  (const float*)d_in[wb + 1],
        (const float*)d_in[wb + 2],  (const float*)d_in[wb + 3],
        (const float*)d_in[wb + 4],  (const float*)d_in[wb + 5],
        (const float*)d_in[wb + 6],  (const float*)d_in[wb + 7],
        (const float*)d_in[wb + 8],  (const float*)d_in[wb + 9],
        (const float*)d_in[wb + 10], (const float*)d_in[wb + 11],
        (const float*)d_in[wb + 12], (const float*)d_in[wb + 13],
        (const float*)d_in[wb + 14], (const float*)d_in[wb + 15],
        (const float*)d_in[wb + 16], (const float*)d_in[wb + 17],
        (const float*)d_in[wb + 18], (const float*)d_in[wb + 19],
        (float*)d_out);
}

// round 2
// speedup vs baseline: 1.5739x; 1.5739x over previous
#include <cuda_runtime.h>

#define NTOK 20
#define NT   24          // padded token stride (floats); rows 96B, 16B-aligned
#define TPB  128

typedef unsigned long long ull;

// ---------- packed f32x2 helpers ----------
__device__ __forceinline__ ull pk2(float lo, float hi) {
    ull r;
    asm("mov.b64 %0, {%1,%2};" : "=l"(r)
        : "r"(__float_as_uint(lo)), "r"(__float_as_uint(hi)));
    return r;
}
__device__ __forceinline__ void upk2(ull v, float& lo, float& hi) {
    unsigned int a, b;
    asm("mov.b64 {%0,%1}, %2;" : "=r"(a), "=r"(b) : "l"(v));
    lo = __uint_as_float(a); hi = __uint_as_float(b);
}
__device__ __forceinline__ void fma2(ull& d, ull a, ull b) {
    asm("fma.rn.f32x2 %0, %1, %2, %0;" : "+l"(d) : "l"(a), "l"(b));
}

// ---------- dense layer, JT=2: thread owns output pair (2p, 2p+1) ----------
// in_sh feature-major [FI][NT], out feature-major [FO][NT]. FO must be even.
template<int FI, int FO, bool RELU>
__device__ __forceinline__ void dense(const float* __restrict__ W,
                                      const float* __restrict__ Bv,
                                      const float* in_sh, float* out_sh) {
    constexpr int P = FO / 2;
    const int tid = threadIdx.x;
    for (int p = tid; p < P; p += TPB) {
        const float2 bj = *reinterpret_cast<const float2*>(Bv + 2 * p);
        ull a0[10], a1[10];
        #pragma unroll
        for (int k = 0; k < 10; k++) { a0[k] = pk2(bj.x, bj.x); a1[k] = pk2(bj.y, bj.y); }
        #pragma unroll 4
        for (int i = 0; i < FI; i++) {
            const float2 wv = *reinterpret_cast<const float2*>(W + i * FO + 2 * p);
            const ull w0 = pk2(wv.x, wv.x);
            const ull w1 = pk2(wv.y, wv.y);
            const ulonglong2* row = reinterpret_cast<const ulonglong2*>(in_sh + i * NT);
            #pragma unroll
            for (int q = 0; q < 5; q++) {
                ulonglong2 v = row[q];
                fma2(a0[2*q],   v.x, w0);
                fma2(a0[2*q+1], v.y, w0);
                fma2(a1[2*q],   v.x, w1);
                fma2(a1[2*q+1], v.y, w1);
            }
        }
        float* o0 = out_sh + (2 * p) * NT;
        float* o1 = out_sh + (2 * p + 1) * NT;
        #pragma unroll
        for (int k = 0; k < 10; k++) {
            float x0, x1, y0, y1;
            upk2(a0[k], x0, x1); upk2(a1[k], y0, y1);
            if (RELU) {
                x0 = fmaxf(x0, 0.f); x1 = fmaxf(x1, 0.f);
                y0 = fmaxf(y0, 0.f); y1 = fmaxf(y1, 0.f);
            }
            *reinterpret_cast<ull*>(o0 + 2 * k) = pk2(x0, x1);
            *reinterpret_cast<ull*>(o1 + 2 * k) = pk2(y0, y1);
        }
    }
}

// ---------- dense with concat input, JT=2: [per-token F1] ++ [token-invariant FG] ----------
template<int F1, int FG, int FO, bool RELU>
__device__ __forceinline__ void dense_cat(const float* __restrict__ W,
                                          const float* __restrict__ Bv,
                                          const float* in_sh, const float* gv,
                                          float* out_sh) {
    constexpr int P = FO / 2;
    const int tid = threadIdx.x;
    for (int p = tid; p < P; p += TPB) {
        // token-invariant half folded into both biases (1 FMA per input, not 20)
        float s0 = Bv[2 * p], s1 = Bv[2 * p + 1];
        #pragma unroll 4
        for (int i = 0; i < FG; i++) {
            const float2 wv = *reinterpret_cast<const float2*>(W + (F1 + i) * FO + 2 * p);
            s0 = fmaf(gv[i], wv.x, s0);
            s1 = fmaf(gv[i], wv.y, s1);
        }
        ull a0[10], a1[10];
        #pragma unroll
        for (int k = 0; k < 10; k++) { a0[k] = pk2(s0, s0); a1[k] = pk2(s1, s1); }
        #pragma unroll 4
        for (int i = 0; i < F1; i++) {
            const float2 wv = *reinterpret_cast<const float2*>(W + i * FO + 2 * p);
            const ull w0 = pk2(wv.x, wv.x);
            const ull w1 = pk2(wv.y, wv.y);
            const ulonglong2* row = reinterpret_cast<const ulonglong2*>(in_sh + i * NT);
            #pragma unroll
            for (int q = 0; q < 5; q++) {
                ulonglong2 v = row[q];
                fma2(a0[2*q],   v.x, w0);
                fma2(a0[2*q+1], v.y, w0);
                fma2(a1[2*q],   v.x, w1);
                fma2(a1[2*q+1], v.y, w1);
            }
        }
        float* o0 = out_sh + (2 * p) * NT;
        float* o1 = out_sh + (2 * p + 1) * NT;
        #pragma unroll
        for (int k = 0; k < 10; k++) {
            float x0, x1, y0, y1;
            upk2(a0[k], x0, x1); upk2(a1[k], y0, y1);
            if (RELU) {
                x0 = fmaxf(x0, 0.f); x1 = fmaxf(x1, 0.f);
                y0 = fmaxf(y0, 0.f); y1 = fmaxf(y1, 0.f);
            }
            *reinterpret_cast<ull*>(o0 + 2 * k) = pk2(x0, x1);
            *reinterpret_cast<ull*>(o1 + 2 * k) = pk2(y0, y1);
        }
    }
}

__global__ void __launch_bounds__(TPB, 4)
sp_kernel(const float* __restrict__ state,
          const float* __restrict__ m1w0, const float* __restrict__ m1b0,
          const float* __restrict__ m1w1, const float* __restrict__ m1b1,
          const float* __restrict__ m2w0, const float* __restrict__ m2b0,
          const float* __restrict__ m2w1, const float* __restrict__ m2b1,
          const float* __restrict__ atw0, const float* __restrict__ atb0,
          const float* __restrict__ atw1, const float* __restrict__ atb1,
          const float* __restrict__ atw2, const float* __restrict__ atb2,
          const float* __restrict__ hpw0, const float* __restrict__ hpb0,
          const float* __restrict__ hpw1, const float* __restrict__ hpb1,
          const float* __restrict__ hpw2, const float* __restrict__ hpb2,
          float* __restrict__ out)
{
    __shared__ __align__(16) float x_sh[13 * NT];
    __shared__ __align__(16) float h1_sh[100 * NT];
    __shared__ __align__(16) float h2_sh[50 * NT];
    __shared__ __align__(16) float tA[150 * NT];
    __shared__ __align__(16) float tB[100 * NT];
    __shared__ float g_sh[100];
    __shared__ float ws_sh[64];
    __shared__ float mask_sh[NTOK];
    __shared__ float se_sh[NTOK];
    __shared__ float w_sh[NTOK];

    const int b   = blockIdx.x;
    const int tid = threadIdx.x;

    // ---- load state tile: 20 tokens x (13 feats + mask), to feature-major ----
    const float* st = state + (size_t)b * (NTOK * 14);
    for (int t = tid; t < NTOK * 14; t += TPB) {
        float v = st[t];
        int n = t / 14, d = t % 14;
        if (d == 13) mask_sh[n] = v;
        else         x_sh[d * NT + n] = v;
    }
    __syncthreads();

    // ---- m1: 13 -> 150 (relu) -> 100 (relu) ----
    dense<13, 150, true>(m1w0, m1b0, x_sh, tA);
    __syncthreads();
    dense<150, 100, true>(m1w1, m1b1, tA, h1_sh);
    __syncthreads();

    // ---- masked mean of h1 over tokens -> g_sh[100] ----
    if (tid < 100) {
        float msum = 0.f;
        #pragma unroll
        for (int n = 0; n < NTOK; n++) msum += mask_sh[n];
        const float inv = (msum > 0.f) ? 1.f / msum : 0.f;
        float gj = 0.f;
        #pragma unroll
        for (int n = 0; n < NTOK; n++) gj += mask_sh[n] * h1_sh[tid * NT + n];
        g_sh[tid] = gj * inv;
    }
    __syncthreads();

    // ---- m2: h1 -> 100 (relu) -> 50 (no relu) ----
    dense<100, 100, true>(m2w0, m2b0, h1_sh, tB);
    __syncthreads();
    dense<100, 50, false>(m2w1, m2b1, tB, h2_sh);
    __syncthreads();

    // ---- attention MLP: concat(h1, g) -> 100 (relu) -> 100 (relu) -> 1 ----
    dense_cat<100, 100, 100, true>(atw0, atb0, h1_sh, g_sh, tA);
    __syncthreads();
    dense<100, 100, true>(atw1, atb1, tA, tB);
    __syncthreads();

    if (tid < NTOK) {
        float s = atb2[0];
        #pragma unroll 4
        for (int i = 0; i < 100; i++) s = fmaf(tB[i * NT + tid], atw2[i], s);
        s *= mask_sh[tid];
        se_sh[tid] = (s != 0.f) ? expf(s) : 0.f;
    }
    __syncthreads();
    if (tid < NTOK) {
        float ssum = 0.f;
        #pragma unroll
        for (int n = 0; n < NTOK; n++) ssum += se_sh[n];
        w_sh[tid] = (ssum > 0.f) ? se_sh[tid] / ssum : 0.f;
    }
    __syncthreads();

    // ---- weighted sum of h2 -> ws_sh[50] ----
    if (tid < 50) {
        float s = 0.f;
        #pragma unroll
        for (int n = 0; n < NTOK; n++) s += w_sh[n] * h2_sh[tid * NT + n];
        ws_sh[tid] = s;
    }
    __syncthreads();

    // ---- head: concat(h2, wsum) -> 100 (relu) -> 100 (relu) -> 7 ----
    dense_cat<50, 50, 100, true>(hpw0, hpb0, h2_sh, ws_sh, tA);
    __syncthreads();
    dense<100, 100, true>(hpw1, hpb1, tA, tB);
    __syncthreads();

    // ---- final 100 -> 7, thread = (token-pair, neuron) ----
    if (tid < 70) {
        const int kp = tid / 7, j = tid % 7;
        ull acc = pk2(hpb2[j], hpb2[j]);
        #pragma unroll 4
        for (int i = 0; i < 100; i++) {
            const float w = hpw2[i * 7 + j];
            ull v = *reinterpret_cast<const ull*>(tB + i * NT + 2 * kp);
            fma2(acc, v, pk2(w, w));
        }
        float a, c; upk2(acc, a, c);
        float* ob = out + (size_t)b * (NTOK * 7);
        ob[(2 * kp)     * 7 + j] = a;
        ob[(2 * kp + 1) * 7 + j] = c;
    }
}

extern "C" void kernel_launch(void* const* d_in, const int* in_sizes, int n_in,
                              void* d_out, int out_size) {
    // state is the only huge tensor (B*20*14 elems); detect its position by size.
    int si, wb;
    if (in_sizes[0] > 1000000) { si = 0;        wb = 1; }
    else                       { si = n_in - 1; wb = 0; }
    const float* state = (const float*)d_in[si];
    const int B = in_sizes[si] / (NTOK * 14);

    sp_kernel<<<B, TPB>>>(
        state,
        (const float*)d_in[wb + 0],  (const float*)d_in[wb + 1],
        (const float*)d_in[wb + 2],  (const float*)d_in[wb + 3],
        (const float*)d_in[wb + 4],  (const float*)d_in[wb + 5],
        (const float*)d_in[wb + 6],  (const float*)d_in[wb + 7],
        (const float*)d_in[wb + 8],  (const float*)d_in[wb + 9],
        (const float*)d_in[wb + 10], (const float*)d_in[wb + 11],
        (const float*)d_in[wb + 12], (const float*)d_in[wb + 13],
        (const float*)d_in[wb + 14], (const float*)d_in[wb + 15],
        (const float*)d_in[wb + 16], (const float*)d_in[wb + 17],
        (const float*)d_in[wb + 18], (const float*)d_in[wb + 19],
        (float*)d_out);
}

// round 3
// speedup vs baseline: 1.8164x; 1.1541x over previous
#include <cuda_runtime.h>

#define NTOK 20
#define NT   20          // token stride in floats (80B rows, 16B-aligned)
#define TPB  128

typedef unsigned long long ull;

// ---------- packed f32x2 helpers ----------
__device__ __forceinline__ ull pk2(float lo, float hi) {
    ull r;
    asm("mov.b64 %0, {%1,%2};" : "=l"(r)
        : "r"(__float_as_uint(lo)), "r"(__float_as_uint(hi)));
    return r;
}
__device__ __forceinline__ void upk2(ull v, float& lo, float& hi) {
    unsigned int a, b;
    asm("mov.b64 {%0,%1}, %2;" : "=r"(a), "=r"(b) : "l"(v));
    lo = __uint_as_float(a); hi = __uint_as_float(b);
}
__device__ __forceinline__ void fma2(ull& d, ull a, ull b) {
    asm("fma.rn.f32x2 %0, %1, %2, %0;" : "+l"(d) : "l"(a), "l"(b));
}

// ---------- dense layer, 2D decomposition ----------
// unit u = (neuron-group q) * 5 + (token-group tg). Thread owns JT neurons x 4 tokens.
// in_sh/out_sh feature-major [F][NT]. FO % JT == 0; (FO/JT)*5 <= ~128 for 1 pass.
template<int FI, int FO, int JT, bool RELU>
__device__ __forceinline__ void dense(const float* __restrict__ W,
                                      const float* __restrict__ Bv,
                                      const float* in_sh, float* out_sh) {
    constexpr int NG = FO / JT;
    constexpr int U  = NG * 5;
    static_assert(FO % JT == 0, "FO divisible by JT");
    const int tid = threadIdx.x;
    for (int u = tid; u < U; u += TPB) {
        const int q  = u / 5;
        const int tg = u % 5;
        const int j0 = q * JT;
        ull acc[JT][2];
        #pragma unroll
        for (int j = 0; j < JT; j++) {
            const float b = Bv[j0 + j];
            acc[j][0] = pk2(b, b);
            acc[j][1] = pk2(b, b);
        }
        const float* wp = W + j0;
        const float* ip = in_sh + 4 * tg;
        #pragma unroll 4
        for (int i = 0; i < FI; i++) {
            const ulonglong2 v = *reinterpret_cast<const ulonglong2*>(ip + i * NT);
            float w[JT];
            if constexpr (JT == 4) {
                const float4 wv = *reinterpret_cast<const float4*>(wp + i * FO);
                w[0] = wv.x; w[1] = wv.y; w[2] = wv.z; w[3] = wv.w;
            } else {
                #pragma unroll
                for (int jj = 0; jj < JT / 2; jj++) {
                    const float2 wv =
                        *reinterpret_cast<const float2*>(wp + i * FO + 2 * jj);
                    w[2 * jj] = wv.x; w[2 * jj + 1] = wv.y;
                }
            }
            #pragma unroll
            for (int j = 0; j < JT; j++) {
                const ull wd = pk2(w[j], w[j]);
                fma2(acc[j][0], v.x, wd);
                fma2(acc[j][1], v.y, wd);
            }
        }
        #pragma unroll
        for (int j = 0; j < JT; j++) {
            float x0, x1, x2, x3;
            upk2(acc[j][0], x0, x1);
            upk2(acc[j][1], x2, x3);
            if (RELU) {
                x0 = fmaxf(x0, 0.f); x1 = fmaxf(x1, 0.f);
                x2 = fmaxf(x2, 0.f); x3 = fmaxf(x3, 0.f);
            }
            ulonglong2 st;
            st.x = pk2(x0, x1);
            st.y = pk2(x2, x3);
            *reinterpret_cast<ulonglong2*>(out_sh + (j0 + j) * NT + 4 * tg) = st;
        }
    }
}

// ---------- fold token-invariant concat half into an effective bias ----------
template<int F1, int FG, int FO>
__device__ __forceinline__ void fold_bias(const float* __restrict__ W,
                                          const float* __restrict__ Bv,
                                          const float* gv, float* fold_sh) {
    for (int j = threadIdx.x; j < FO; j += TPB) {
        float s = Bv[j];
        #pragma unroll 4
        for (int i = 0; i < FG; i++) s = fmaf(gv[i], W[(F1 + i) * FO + j], s);
        fold_sh[j] = s;
    }
}

__global__ void __launch_bounds__(TPB, 5)
sp_kernel(const float* __restrict__ state,
          const float* __restrict__ m1w0, const float* __restrict__ m1b0,
          const float* __restrict__ m1w1, const float* __restrict__ m1b1,
          const float* __restrict__ m2w0, const float* __restrict__ m2b0,
          const float* __restrict__ m2w1, const float* __restrict__ m2b1,
          const float* __restrict__ atw0, const float* __restrict__ atb0,
          const float* __restrict__ atw1, const float* __restrict__ atb1,
          const float* __restrict__ atw2, const float* __restrict__ atb2,
          const float* __restrict__ hpw0, const float* __restrict__ hpb0,
          const float* __restrict__ hpw1, const float* __restrict__ hpb1,
          const float* __restrict__ hpw2, const float* __restrict__ hpb2,
          float* __restrict__ out)
{
    __shared__ __align__(16) float x_sh[13 * NT];
    __shared__ __align__(16) float h1_sh[100 * NT];
    __shared__ __align__(16) float h2_sh[50 * NT];
    __shared__ __align__(16) float tA[150 * NT];
    __shared__ __align__(16) float tB[100 * NT];
    __shared__ __align__(16) float g_sh[100];
    __shared__ __align__(16) float fold_sh[100];
    __shared__ __align__(16) float ws_sh[52];
    __shared__ float mask_sh[NTOK];
    __shared__ float se_sh[NTOK];
    __shared__ float w_sh[NTOK];

    const int b   = blockIdx.x;
    const int tid = threadIdx.x;

    // ---- load state tile: 20 tokens x (13 feats + mask), to feature-major ----
    const float* st = state + (size_t)b * (NTOK * 14);
    for (int t = tid; t < NTOK * 14; t += TPB) {
        const float v = st[t];
        const int n = t / 14, d = t % 14;
        if (d == 13) mask_sh[n] = v;
        else         x_sh[d * NT + n] = v;
    }
    __syncthreads();

    // ---- m1: 13 -> 150 (relu) -> 100 (relu) ----
    dense<13, 150, 6, true>(m1w0, m1b0, x_sh, tA);
    __syncthreads();
    dense<150, 100, 4, true>(m1w1, m1b1, tA, h1_sh);
    __syncthreads();

    // ---- masked mean of h1 over tokens -> g_sh[100] ----
    if (tid < 100) {
        float msum = 0.f;
        #pragma unroll
        for (int n = 0; n < NTOK; n++) msum += mask_sh[n];
        const float inv = (msum > 0.f) ? 1.f / msum : 0.f;
        float gj = 0.f;
        #pragma unroll
        for (int n = 0; n < NTOK; n++) gj += mask_sh[n] * h1_sh[tid * NT + n];
        g_sh[tid] = gj * inv;
    }
    __syncthreads();

    // ---- fold at0's global half while g is fresh ----
    fold_bias<100, 100, 100>(atw0, atb0, g_sh, fold_sh);
    __syncthreads();

    // ---- m2: h1 -> 100 (relu) -> 50 (no relu) ----
    dense<100, 100, 4, true>(m2w0, m2b0, h1_sh, tB);
    __syncthreads();
    dense<100, 50, 2, false>(m2w1, m2b1, tB, h2_sh);
    __syncthreads();

    // ---- attention MLP: concat(h1, g) -> 100 (relu) -> 100 (relu) -> 1 ----
    dense<100, 100, 4, true>(atw0, fold_sh, h1_sh, tA);
    __syncthreads();
    dense<100, 100, 4, true>(atw1, atb1, tA, tB);
    __syncthreads();

    if (tid < NTOK) {
        float s = atb2[0];
        #pragma unroll 4
        for (int i = 0; i < 100; i++) s = fmaf(tB[i * NT + tid], atw2[i], s);
        s *= mask_sh[tid];
        se_sh[tid] = (s != 0.f) ? expf(s) : 0.f;
    }
    __syncthreads();
    if (tid < NTOK) {
        float ssum = 0.f;
        #pragma unroll
        for (int n = 0; n < NTOK; n++) ssum += se_sh[n];
        w_sh[tid] = (ssum > 0.f) ? se_sh[tid] / ssum : 0.f;
    }
    __syncthreads();

    // ---- weighted sum of h2 -> ws_sh[50] ----
    if (tid < 50) {
        float s = 0.f;
        #pragma unroll
        for (int n = 0; n < NTOK; n++) s += w_sh[n] * h2_sh[tid * NT + n];
        ws_sh[tid] = s;
    }
    __syncthreads();

    // ---- fold hp0's weighted-sum half ----
    fold_bias<50, 50, 100>(hpw0, hpb0, ws_sh, fold_sh);
    __syncthreads();

    // ---- head: concat(h2, wsum) -> 100 (relu) -> 100 (relu) -> 7 ----
    dense<50, 100, 4, true>(hpw0, fold_sh, h2_sh, tA);
    __syncthreads();
    dense<100, 100, 4, true>(hpw1, hpb1, tA, tB);
    __syncthreads();

    // ---- final 100 -> 7, thread = (token-pair, neuron) ----
    if (tid < 70) {
        const int kp = tid / 7, j = tid % 7;
        ull acc = pk2(hpb2[j], hpb2[j]);
        #pragma unroll 4
        for (int i = 0; i < 100; i++) {
            const float w = hpw2[i * 7 + j];
            const ull v = *reinterpret_cast<const ull*>(tB + i * NT + 2 * kp);
            fma2(acc, v, pk2(w, w));
        }
        float a, c; upk2(acc, a, c);
        float* ob = out + (size_t)b * (NTOK * 7);
        ob[(2 * kp)     * 7 + j] = a;
        ob[(2 * kp + 1) * 7 + j] = c;
    }
}

extern "C" void kernel_launch(void* const* d_in, const int* in_sizes, int n_in,
                              void* d_out, int out_size) {
    // state is the only huge tensor (B*20*14 elems); detect its position by size.
    int si, wb;
    if (in_sizes[0] > 1000000) { si = 0;        wb = 1; }
    else                       { si = n_in - 1; wb = 0; }
    const float* state = (const float*)d_in[si];
    const int B = in_sizes[si] / (NTOK * 14);

    sp_kernel<<<B, TPB>>>(
        state,
        (const float*)d_in[wb + 0],  (const float*)d_in[wb + 1],
        (const float*)d_in[wb + 2],  (const float*)d_in[wb + 3],
        (const float*)d_in[wb + 4],  (const float*)d_in[wb + 5],
        (const float*)d_in[wb + 6],  (const float*)d_in[wb + 7],
        (const float*)d_in[wb + 8],  (const float*)d_in[wb + 9],
        (const float*)d_in[wb + 10], (const float*)d_in[wb + 11],
        (const float*)d_in[wb + 12], (const float*)d_in[wb + 13],
        (const float*)d_in[wb + 14], (const float*)d_in[wb + 15],
        (const float*)d_in[wb + 16], (const float*)d_in[wb + 17],
        (const float*)d_in[wb + 18], (const float*)d_in[wb + 19],
        (float*)d_out);
}